// round 12
// baseline (speedup 1.0000x reference)
#include <cuda_runtime.h>
#include <math.h>

// Problem constants
#define LSIG     524288
#define NFFT     1024
#define NC       512
#define HOP      256
#define NB       32
#define FOUT     512
#define TOUT     2048
#define FPB      8            // output frames per block
#define PADBUF   576          // 512 + 64 pad (9-elem rows), float2 elems

// fp64-accurate tables
__device__ float  d_win[NFFT];
__device__ float2 d_tw[256];     // exp(-2*pi*i*k/512)
__device__ float2 d_unt[513];    // -i*exp(-i*pi*k/512)

__global__ void init_tables_kernel() {
    int i = blockIdx.x * 128 + threadIdx.x;   // 8 x 128 = 0..1023
    const double PI = 3.14159265358979323846;
    d_win[i] = (float)(0.5 * (1.0 - cos(2.0 * PI * (double)i / 1024.0)));
    if (i < 256) {
        double th = -2.0 * PI * (double)i / 512.0;
        d_tw[i] = make_float2((float)cos(th), (float)sin(th));
    }
    if (i < 513) {
        double th = PI * (double)i / 512.0;
        d_unt[i] = make_float2((float)(-sin(th)), (float)(-cos(th)));
    }
}

// Butterfly identical to the radix-2 reference: a=lower, c=upper.
#define BFLY(p, qq, w) do {                                   \
    float tr = xr[qq] * (w).x - xi[qq] * (w).y;               \
    float ti = xr[qq] * (w).y + xi[qq] * (w).x;               \
    float ax = xr[p], ay = xi[p];                             \
    xr[p]  = ax + tr;  xi[p]  = ay + ti;                      \
    xr[qq] = ax - tr;  xi[qq] = ay - ti;                      \
} while (0)

// Intra-group barrier: 64 threads (2 warps), named barrier q+1.
#define GBAR() asm volatile("bar.sync %0, 64;" :: "r"(q + 1) : "memory")

// One CTA = (b, group of 8 output frames). 4 sub-groups of 64 threads each
// run one 512-pt FFT with 8 complex points/thread in registers; smem only
// for 3 stage-exchanges, held as interleaved float2 (64-bit LDS/STS).
__global__ __launch_bounds__(256) void stft_fused_kernel(
    const float* __restrict__ x, float* __restrict__ out)
{
    extern __shared__ float sm[];
    const int tid = threadIdx.x;
    const int q   = tid >> 6;        // group 0..3
    const int gt  = tid & 63;        // thread in group
    const int g   = blockIdx.x;      // 0..255
    const int b   = blockIdx.y;      // 0..31

    float2* A2 = reinterpret_cast<float2*>(sm) + q * (2 * PADBUF);
    float2* B2 = A2 + PADBUF;
    float*  ph = sm + 4 * (4 * PADBUF);          // [9][513]
    float*  mg = ph + 9 * 513;                   // [8][513]

    const float* xb = x + (size_t)b * LSIG;
    const bool edge = (g == 0) || (g == (TOUT / FPB - 1));

    for (int r = 0; r < 3; r++) {
        const int f = 4 * r + q;                 // spectrum slot 0..8
        const bool active = (f <= FPB);
        const int t    = FPB * g + f;
        const int base = t * HOP - (NFFT / 2);

        if (active) {
            // ---- load: windowed input, linear complex order -> B2 ----
            if (edge) {
                #pragma unroll
                for (int jj = 0; jj < 8; jj++) {
                    int n  = 64 * jj + gt;
                    int j0 = 2 * n, j1 = 2 * n + 1;
                    int p0 = base + j0;
                    int p1 = base + j1;
                    if (p0 < 0) p0 = -p0;
                    if (p0 >= LSIG) p0 = 2 * LSIG - 2 - p0;
                    if (p1 < 0) p1 = -p1;
                    if (p1 >= LSIG) p1 = 2 * LSIG - 2 - p1;
                    B2[n] = make_float2(xb[p0] * d_win[j0],
                                        xb[p1] * d_win[j1]);
                }
            } else {
                const float2* xv = reinterpret_cast<const float2*>(xb + base);
                const float2* wv = reinterpret_cast<const float2*>(d_win);
                #pragma unroll
                for (int jj = 0; jj < 8; jj++) {
                    int n = 64 * jj + gt;
                    float2 z = xv[n];
                    float2 w = wv[n];
                    B2[n] = make_float2(z.x * w.x, z.y * w.y);
                }
            }
            GBAR();

            float xr[8], xi[8];

            // ---- phase A: gather bit-reversed, stages 1-3 in regs ----
            const int br6 = __brev(gt) >> 26;
            const int BR3[8] = {0, 4, 2, 6, 1, 5, 3, 7};
            #pragma unroll
            for (int j = 0; j < 8; j++) {
                float2 z = B2[(BR3[j] << 6) | br6];
                xr[j] = z.x;
                xi[j] = z.y;
            }
            { float2 w = d_tw[0];
              BFLY(0,1,w); BFLY(2,3,w); BFLY(4,5,w); BFLY(6,7,w); }
            { float2 w0 = d_tw[0], w1 = d_tw[128];
              BFLY(0,2,w0); BFLY(1,3,w1); BFLY(4,6,w0); BFLY(5,7,w1); }
            { float2 w0 = d_tw[0], w1 = d_tw[64], w2 = d_tw[128], w3 = d_tw[192];
              BFLY(0,4,w0); BFLY(1,5,w1); BFLY(2,6,w2); BFLY(3,7,w3); }
            #pragma unroll
            for (int j = 0; j < 8; j++)
                A2[9 * gt + j] = make_float2(xr[j], xi[j]);
            GBAR();

            // ---- phase B: i = 64H + 8j + L, stages 4-6 ----
            const int H = gt >> 3, L = gt & 7;
            #pragma unroll
            for (int j = 0; j < 8; j++) {
                float2 z = A2[72 * H + 9 * j + L];   // addr1(64H+8j+L)
                xr[j] = z.x;
                xi[j] = z.y;
            }
            { float2 w = d_tw[L << 5];
              BFLY(0,1,w); BFLY(2,3,w); BFLY(4,5,w); BFLY(6,7,w); }
            { float2 w0 = d_tw[L << 4], w1 = d_tw[(8 + L) << 4];
              BFLY(0,2,w0); BFLY(1,3,w1); BFLY(4,6,w0); BFLY(5,7,w1); }
            { float2 w0 = d_tw[L << 3],        w1 = d_tw[(8 + L) << 3];
              float2 w2 = d_tw[(16 + L) << 3], w3 = d_tw[(24 + L) << 3];
              BFLY(0,4,w0); BFLY(1,5,w1); BFLY(2,6,w2); BFLY(3,7,w3); }
            #pragma unroll
            for (int j = 0; j < 8; j++)
                B2[72 * j + 9 * L + H] = make_float2(xr[j], xi[j]);
            GBAR();

            // ---- phase C: i = 64j + gt, stages 7-9, natural order ----
            #pragma unroll
            for (int j = 0; j < 8; j++) {
                float2 z = B2[9 * gt + j];           // addr2(64j+gt)
                xr[j] = z.x;
                xi[j] = z.y;
            }
            { float2 w = d_tw[gt << 2];
              BFLY(0,1,w); BFLY(2,3,w); BFLY(4,5,w); BFLY(6,7,w); }
            { float2 w0 = d_tw[gt << 1], w1 = d_tw[(64 + gt) << 1];
              BFLY(0,2,w0); BFLY(1,3,w1); BFLY(4,6,w0); BFLY(5,7,w1); }
            { float2 w0 = d_tw[gt],       w1 = d_tw[64 + gt];
              float2 w2 = d_tw[128 + gt], w3 = d_tw[192 + gt];
              BFLY(0,4,w0); BFLY(1,5,w1); BFLY(2,6,w2); BFLY(3,7,w3); }
            #pragma unroll
            for (int j = 0; j < 8; j++)
                A2[64 * j + gt] = make_float2(xr[j], xi[j]);
            GBAR();

            // ---- untangle + phase/log-mag to smem (phase math verbatim) --
            #pragma unroll
            for (int rr = 0; rr < 8; rr++) {
                int k = 64 * rr + gt + 1;        // 1..512
                int km = (NC - k) & (NC - 1);
                float2 Zk = A2[k & (NC - 1)];
                float2 Zm = A2[km];
                float ar = 0.5f * (Zk.x + Zm.x);
                float ai = 0.5f * (Zk.y - Zm.y);
                float br = 0.5f * (Zk.x - Zm.x);
                float bi = 0.5f * (Zk.y + Zm.y);
                float2 C = d_unt[k];
                float vr = ar + C.x * br - C.y * bi;
                float vi = ai + C.x * bi + C.y * br;
                if (k == 512) vi = 0.0f;         // Nyquist analytically real
                ph[f * 513 + (k - 1)] = atan2f(vi, vr);
                if (f >= 1) {
                    float m2 = vr * vr + vi * vi;
                    mg[(f - 1) * 513 + (k - 1)] =
                        (0.5f * __logf(fmaxf(m2, 1e-14f)) + 17.0f) * (1.0f / 23.0f);
                }
            }
            // No barrier here: A2 next written in phase A after the
            // post-load GBAR; B2 next written by the load after the
            // post-C GBAR; ph/mg read only after __syncthreads below.
        }
    }

    __syncthreads();   // staging (ph/mg) is read across groups below

    // ---- writeback: per-thread 8 consecutive t's, float4 stores ----
    const float PI_F   = 3.14159274101257324f;
    const float TWO_PI = 6.28318548202514648f;

    #pragma unroll
    for (int r = 0; r < 2; r++) {
        int fo = tid + r * 256;                  // output freq 0..511
        size_t omag = (((size_t)b * 2 + 0) * FOUT + fo) * TOUT + FPB * g;
        size_t opha = (((size_t)b * 2 + 1) * FOUT + fo) * TOUT + FPB * g;

        float m[FPB], p[FPB];
        #pragma unroll
        for (int j = 0; j < FPB; j++) {
            m[j] = mg[j * 513 + fo];
            float p0 = ph[j * 513 + fo];
            float p1 = ph[(j + 1) * 513 + fo];
            float dd = p1 - p0;
            float res;
            if (fabsf(dd) < PI_F) {
                res = dd;
            } else {
                float rr = fmodf(dd + PI_F, TWO_PI);
                if (rr < 0.0f) rr += TWO_PI;
                float ddmod = rr - PI_F;
                if (ddmod == -PI_F && dd > 0.0f) ddmod = PI_F;
                res = ddmod;
            }
            p[j] = res;
        }
        *reinterpret_cast<float4*>(out + omag) =
            make_float4(m[0], m[1], m[2], m[3]);
        *reinterpret_cast<float4*>(out + omag + 4) =
            make_float4(m[4], m[5], m[6], m[7]);
        *reinterpret_cast<float4*>(out + opha) =
            make_float4(p[0], p[1], p[2], p[3]);
        *reinterpret_cast<float4*>(out + opha + 4) =
            make_float4(p[4], p[5], p[6], p[7]);
    }
}

extern "C" void kernel_launch(void* const* d_in, const int* in_sizes, int n_in,
                              void* d_out, int out_size)
{
    const float* x = (const float*)d_in[0];
    float* out = (float*)d_out;

    const int smem_bytes = (4 * 4 * PADBUF + 9 * 513 + 8 * 513) * 4;
    cudaFuncSetAttribute(stft_fused_kernel,
                         cudaFuncAttributeMaxDynamicSharedMemorySize,
                         smem_bytes);

    init_tables_kernel<<<8, 128>>>();

    dim3 grid(TOUT / FPB, NB);     // (256, 32)
    stft_fused_kernel<<<grid, 256, smem_bytes>>>(x, out);
}

// round 13
// speedup vs baseline: 1.1244x; 1.1244x over previous
#include <cuda_runtime.h>
#include <math.h>

// Problem constants
#define LSIG     524288
#define NFFT     1024
#define NC       512
#define HOP      256
#define NB       32
#define FOUT     512
#define TOUT     2048
#define FPB      8            // output frames per block
#define SBUF     576          // in-place exchange buffer floats (9-elem rows)

// fp64-accurate tables
__device__ float  d_win[NFFT];
__device__ float2 d_tw[256];     // exp(-2*pi*i*k/512)
__device__ float2 d_unt[513];    // -i*exp(-i*pi*k/512)

__global__ void init_tables_kernel() {
    int i = blockIdx.x * 128 + threadIdx.x;   // 8 x 128 = 0..1023
    const double PI = 3.14159265358979323846;
    d_win[i] = (float)(0.5 * (1.0 - cos(2.0 * PI * (double)i / 1024.0)));
    if (i < 256) {
        double th = -2.0 * PI * (double)i / 512.0;
        d_tw[i] = make_float2((float)cos(th), (float)sin(th));
    }
    if (i < 513) {
        double th = PI * (double)i / 512.0;
        d_unt[i] = make_float2((float)(-sin(th)), (float)(-cos(th)));
    }
}

// Butterfly identical to the radix-2 reference: a=lower, c=upper.
#define BFLY(p, qq, w) do {                                   \
    float tr = xr[qq] * (w).x - xi[qq] * (w).y;               \
    float ti = xr[qq] * (w).y + xi[qq] * (w).x;               \
    float ax = xr[p], ay = xi[p];                             \
    xr[p]  = ax + tr;  xi[p]  = ay + ti;                      \
    xr[qq] = ax - tr;  xi[qq] = ay - ti;                      \
} while (0)

// Intra-group barrier: 64 threads (2 warps), named barrier q+1.
#define GBAR() asm volatile("bar.sync %0, 64;" :: "r"(q + 1) : "memory")

// Storage swizzle for the input-order buffer: inject bit5 into bit0 so the
// bit-reversed gather is bank-conflict-free. Injective (GF(2) bijection).
__device__ __forceinline__ int tau(int n) { return n ^ ((n >> 5) & 1); }

// One CTA = (b, 8 output frames). 3 groups of 64 threads; each group runs
// 3 frames (9 total, zero idle slots). 512-pt FFT with 8 complex pts/thread
// in registers; ONE in-place smem exchange buffer per group (scalar split,
// conflict-free), read-all / GBAR / write-all per phase.
__global__ __launch_bounds__(192) void stft_fused_kernel(
    const float* __restrict__ x, float* __restrict__ out)
{
    extern __shared__ float sm[];
    const int tid = threadIdx.x;
    const int q   = tid / 64;        // group 0..2
    const int gt  = tid % 64;        // thread in group
    const int g   = blockIdx.x;      // 0..255
    const int b   = blockIdx.y;      // 0..31

    float* Sr = sm + q * (2 * SBUF);
    float* Si = Sr + SBUF;
    float* ph = sm + 3 * (2 * SBUF);            // [9][513]
    float* mg = ph + 9 * 513;                   // [8][513]

    const float* xb = x + (size_t)b * LSIG;
    const bool edge = (g == 0) || (g == (TOUT / FPB - 1));

    #pragma unroll
    for (int r = 0; r < 3; r++) {
        const int f = 3 * r + q;                 // spectrum slot 0..8, all live
        const int t    = FPB * g + f;
        const int base = t * HOP - (NFFT / 2);

        // ---- load: windowed input, tau-swizzled linear order ----
        if (edge) {
            #pragma unroll
            for (int jj = 0; jj < 8; jj++) {
                int n  = 64 * jj + gt;
                int j0 = 2 * n, j1 = 2 * n + 1;
                int p0 = base + j0;
                int p1 = base + j1;
                if (p0 < 0) p0 = -p0;
                if (p0 >= LSIG) p0 = 2 * LSIG - 2 - p0;
                if (p1 < 0) p1 = -p1;
                if (p1 >= LSIG) p1 = 2 * LSIG - 2 - p1;
                int a = tau(n);
                Sr[a] = xb[p0] * d_win[j0];
                Si[a] = xb[p1] * d_win[j1];
            }
        } else {
            const float2* xv = reinterpret_cast<const float2*>(xb + base);
            const float2* wv = reinterpret_cast<const float2*>(d_win);
            #pragma unroll
            for (int jj = 0; jj < 8; jj++) {
                int n = 64 * jj + gt;
                float2 z = xv[n];
                float2 w = wv[n];
                int a = tau(n);
                Sr[a] = z.x * w.x;
                Si[a] = z.y * w.y;
            }
        }
        GBAR();

        float xr[8], xi[8];

        // ---- phase A: gather bit-reversed (tau'd), stages 1-3 ----
        const int br6 = __brev(gt) >> 26;
        const int BR3[8] = {0, 4, 2, 6, 1, 5, 3, 7};
        #pragma unroll
        for (int j = 0; j < 8; j++) {
            int a = tau((BR3[j] << 6) | br6);
            xr[j] = Sr[a];
            xi[j] = Si[a];
        }
        { float2 w = d_tw[0];
          BFLY(0,1,w); BFLY(2,3,w); BFLY(4,5,w); BFLY(6,7,w); }
        { float2 w0 = d_tw[0], w1 = d_tw[128];
          BFLY(0,2,w0); BFLY(1,3,w1); BFLY(4,6,w0); BFLY(5,7,w1); }
        { float2 w0 = d_tw[0], w1 = d_tw[64], w2 = d_tw[128], w3 = d_tw[192];
          BFLY(0,4,w0); BFLY(1,5,w1); BFLY(2,6,w2); BFLY(3,7,w3); }
        GBAR();                                   // all reads done
        #pragma unroll
        for (int j = 0; j < 8; j++) {             // addr1(8gt+j) = 9gt+j
            Sr[9 * gt + j] = xr[j];
            Si[9 * gt + j] = xi[j];
        }
        GBAR();

        // ---- phase B: i = 64H + 8j + L, stages 4-6 ----
        const int H = gt >> 3, L = gt & 7;
        #pragma unroll
        for (int j = 0; j < 8; j++) {
            int a = 72 * H + 9 * j + L;           // addr1(64H+8j+L)
            xr[j] = Sr[a];
            xi[j] = Si[a];
        }
        { float2 w = d_tw[L << 5];
          BFLY(0,1,w); BFLY(2,3,w); BFLY(4,5,w); BFLY(6,7,w); }
        { float2 w0 = d_tw[L << 4], w1 = d_tw[(8 + L) << 4];
          BFLY(0,2,w0); BFLY(1,3,w1); BFLY(4,6,w0); BFLY(5,7,w1); }
        { float2 w0 = d_tw[L << 3],        w1 = d_tw[(8 + L) << 3];
          float2 w2 = d_tw[(16 + L) << 3], w3 = d_tw[(24 + L) << 3];
          BFLY(0,4,w0); BFLY(1,5,w1); BFLY(2,6,w2); BFLY(3,7,w3); }
        GBAR();
        #pragma unroll
        for (int j = 0; j < 8; j++) {             // addr2(64H+8j+L)
            Sr[72 * j + 9 * L + H] = xr[j];
            Si[72 * j + 9 * L + H] = xi[j];
        }
        GBAR();

        // ---- phase C: i = 64j + gt, stages 7-9, natural order out ----
        #pragma unroll
        for (int j = 0; j < 8; j++) {
            int a = 9 * gt + j;                   // addr2(64j+gt)
            xr[j] = Sr[a];
            xi[j] = Si[a];
        }
        { float2 w = d_tw[gt << 2];
          BFLY(0,1,w); BFLY(2,3,w); BFLY(4,5,w); BFLY(6,7,w); }
        { float2 w0 = d_tw[gt << 1], w1 = d_tw[(64 + gt) << 1];
          BFLY(0,2,w0); BFLY(1,3,w1); BFLY(4,6,w0); BFLY(5,7,w1); }
        { float2 w0 = d_tw[gt],       w1 = d_tw[64 + gt];
          float2 w2 = d_tw[128 + gt], w3 = d_tw[192 + gt];
          BFLY(0,4,w0); BFLY(1,5,w1); BFLY(2,6,w2); BFLY(3,7,w3); }
        GBAR();
        #pragma unroll
        for (int j = 0; j < 8; j++) {             // plain Z[64j+gt]
            Sr[64 * j + gt] = xr[j];
            Si[64 * j + gt] = xi[j];
        }
        GBAR();

        // ---- untangle + phase/log-mag to staging (phase math verbatim) ---
        #pragma unroll
        for (int rr = 0; rr < 8; rr++) {
            int k = 64 * rr + gt + 1;             // 1..512
            int km = (NC - k) & (NC - 1);
            int kk = k & (NC - 1);
            float ar = 0.5f * (Sr[kk] + Sr[km]);
            float ai = 0.5f * (Si[kk] - Si[km]);
            float br = 0.5f * (Sr[kk] - Sr[km]);
            float bi = 0.5f * (Si[kk] + Si[km]);
            float2 C = d_unt[k];
            float vr = ar + C.x * br - C.y * bi;
            float vi = ai + C.x * bi + C.y * br;
            if (k == 512) vi = 0.0f;              // Nyquist analytically real
            ph[f * 513 + (k - 1)] = atan2f(vi, vr);
            if (f >= 1) {
                float m2 = vr * vr + vi * vi;
                mg[(f - 1) * 513 + (k - 1)] =
                    (0.5f * __logf(fmaxf(m2, 1e-14f)) + 17.0f) * (1.0f / 23.0f);
            }
        }
        GBAR();    // S reused by next round's load
    }

    __syncthreads();   // staging (ph/mg) is read across groups below

    // ---- writeback: per-thread 8 consecutive t's, float4 stores ----
    const float PI_F   = 3.14159274101257324f;
    const float TWO_PI = 6.28318548202514648f;

    for (int fo = tid; fo < FOUT; fo += 192) {
        size_t omag = (((size_t)b * 2 + 0) * FOUT + fo) * TOUT + FPB * g;
        size_t opha = (((size_t)b * 2 + 1) * FOUT + fo) * TOUT + FPB * g;

        float m[FPB], p[FPB];
        #pragma unroll
        for (int j = 0; j < FPB; j++) {
            m[j] = mg[j * 513 + fo];
            float p0 = ph[j * 513 + fo];
            float p1 = ph[(j + 1) * 513 + fo];
            float dd = p1 - p0;
            float res;
            if (fabsf(dd) < PI_F) {
                res = dd;
            } else {
                float rr = fmodf(dd + PI_F, TWO_PI);
                if (rr < 0.0f) rr += TWO_PI;
                float ddmod = rr - PI_F;
                if (ddmod == -PI_F && dd > 0.0f) ddmod = PI_F;
                res = ddmod;
            }
            p[j] = res;
        }
        *reinterpret_cast<float4*>(out + omag) =
            make_float4(m[0], m[1], m[2], m[3]);
        *reinterpret_cast<float4*>(out + omag + 4) =
            make_float4(m[4], m[5], m[6], m[7]);
        *reinterpret_cast<float4*>(out + opha) =
            make_float4(p[0], p[1], p[2], p[3]);
        *reinterpret_cast<float4*>(out + opha + 4) =
            make_float4(p[4], p[5], p[6], p[7]);
    }
}

extern "C" void kernel_launch(void* const* d_in, const int* in_sizes, int n_in,
                              void* d_out, int out_size)
{
    const float* x = (const float*)d_in[0];
    float* out = (float*)d_out;

    // 3 groups * 2 arrays * 576 + ph 9*513 + mg 8*513 floats = 48708 B
    const int smem_bytes = (3 * 2 * SBUF + 9 * 513 + 8 * 513) * 4;
    cudaFuncSetAttribute(stft_fused_kernel,
                         cudaFuncAttributeMaxDynamicSharedMemorySize,
                         smem_bytes);

    init_tables_kernel<<<8, 128>>>();

    dim3 grid(TOUT / FPB, NB);     // (256, 32)
    stft_fused_kernel<<<grid, 192, smem_bytes>>>(x, out);
}

// round 14
// speedup vs baseline: 1.1302x; 1.0052x over previous
#include <cuda_runtime.h>
#include <cuda_fp16.h>
#include <math.h>

// Problem constants
#define LSIG     524288
#define NFFT     1024
#define NC       512
#define HOP      256
#define NB       32
#define FOUT     512
#define TOUT     2048
#define FPB      8            // output frames per block
#define SBUF     576          // in-place exchange buffer floats (9-elem rows)

// fp64-accurate tables
__device__ float  d_win[NFFT];
__device__ float2 d_tw[256];     // exp(-2*pi*i*k/512)
__device__ float2 d_unt[513];    // -i*exp(-i*pi*k/512)

__global__ void init_tables_kernel() {
    int i = blockIdx.x * 128 + threadIdx.x;   // 8 x 128 = 0..1023
    const double PI = 3.14159265358979323846;
    d_win[i] = (float)(0.5 * (1.0 - cos(2.0 * PI * (double)i / 1024.0)));
    if (i < 256) {
        double th = -2.0 * PI * (double)i / 512.0;
        d_tw[i] = make_float2((float)cos(th), (float)sin(th));
    }
    if (i < 513) {
        double th = PI * (double)i / 512.0;
        d_unt[i] = make_float2((float)(-sin(th)), (float)(-cos(th)));
    }
}

// Butterfly identical to the radix-2 reference: a=lower, c=upper.
#define BFLY(p, qq, w) do {                                   \
    float tr = xr[qq] * (w).x - xi[qq] * (w).y;               \
    float ti = xr[qq] * (w).y + xi[qq] * (w).x;               \
    float ax = xr[p], ay = xi[p];                             \
    xr[p]  = ax + tr;  xi[p]  = ay + ti;                      \
    xr[qq] = ax - tr;  xi[qq] = ay - ti;                      \
} while (0)

// Intra-group barrier: 64 threads (2 warps), named barrier q+1.
#define GBAR() asm volatile("bar.sync %0, 64;" :: "r"(q + 1) : "memory")

// Storage swizzle for the input-order buffer: inject bit5 into bit0 so the
// bit-reversed gather is bank-conflict-free. Injective (GF(2) bijection).
__device__ __forceinline__ int tau(int n) { return n ^ ((n >> 5) & 1); }

// One CTA = (b, 8 output frames). 3 groups of 64 threads; each group runs
// 3 frames (9 total, zero idle slots). 512-pt FFT with 8 complex pts/thread
// in registers; ONE in-place smem exchange buffer per group.
__global__ __launch_bounds__(192, 5) void stft_fused_kernel(
    const float* __restrict__ x, float* __restrict__ out)
{
    extern __shared__ float sm[];
    const int tid = threadIdx.x;
    const int q   = tid / 64;        // group 0..2
    const int gt  = tid % 64;        // thread in group
    const int g   = blockIdx.x;      // 0..255
    const int b   = blockIdx.y;      // 0..31

    float*  Sr = sm + q * (2 * SBUF);
    float*  Si = Sr + SBUF;
    float*  ph = sm + 3 * (2 * SBUF);              // [9][513] float
    __half* mg = (__half*)(ph + 9 * 513);          // [8][513] half

    const float* xb = x + (size_t)b * LSIG;
    const bool edge = (g == 0) || (g == (TOUT / FPB - 1));

    #pragma unroll
    for (int r = 0; r < 3; r++) {
        const int f = 3 * r + q;                 // spectrum slot 0..8, all live
        const int t    = FPB * g + f;
        const int base = t * HOP - (NFFT / 2);

        // ---- load: windowed input, tau-swizzled linear order ----
        if (edge) {
            #pragma unroll
            for (int jj = 0; jj < 8; jj++) {
                int n  = 64 * jj + gt;
                int j0 = 2 * n, j1 = 2 * n + 1;
                int p0 = base + j0;
                int p1 = base + j1;
                if (p0 < 0) p0 = -p0;
                if (p0 >= LSIG) p0 = 2 * LSIG - 2 - p0;
                if (p1 < 0) p1 = -p1;
                if (p1 >= LSIG) p1 = 2 * LSIG - 2 - p1;
                int a = tau(n);
                Sr[a] = xb[p0] * d_win[j0];
                Si[a] = xb[p1] * d_win[j1];
            }
        } else {
            const float2* xv = reinterpret_cast<const float2*>(xb + base);
            const float2* wv = reinterpret_cast<const float2*>(d_win);
            #pragma unroll
            for (int jj = 0; jj < 8; jj++) {
                int n = 64 * jj + gt;
                float2 z = xv[n];
                float2 w = wv[n];
                int a = tau(n);
                Sr[a] = z.x * w.x;
                Si[a] = z.y * w.y;
            }
        }
        GBAR();

        float xr[8], xi[8];

        // ---- phase A: gather bit-reversed (tau'd), stages 1-3 ----
        const int br6 = __brev(gt) >> 26;
        const int BR3[8] = {0, 4, 2, 6, 1, 5, 3, 7};
        #pragma unroll
        for (int j = 0; j < 8; j++) {
            int a = tau((BR3[j] << 6) | br6);
            xr[j] = Sr[a];
            xi[j] = Si[a];
        }
        { float2 w = d_tw[0];
          BFLY(0,1,w); BFLY(2,3,w); BFLY(4,5,w); BFLY(6,7,w); }
        { float2 w0 = d_tw[0], w1 = d_tw[128];
          BFLY(0,2,w0); BFLY(1,3,w1); BFLY(4,6,w0); BFLY(5,7,w1); }
        { float2 w0 = d_tw[0], w1 = d_tw[64], w2 = d_tw[128], w3 = d_tw[192];
          BFLY(0,4,w0); BFLY(1,5,w1); BFLY(2,6,w2); BFLY(3,7,w3); }
        GBAR();                                   // all reads done
        #pragma unroll
        for (int j = 0; j < 8; j++) {             // addr1(8gt+j) = 9gt+j
            Sr[9 * gt + j] = xr[j];
            Si[9 * gt + j] = xi[j];
        }
        GBAR();

        // ---- phase B: i = 64H + 8j + L, stages 4-6 ----
        const int H = gt >> 3, L = gt & 7;
        #pragma unroll
        for (int j = 0; j < 8; j++) {
            int a = 72 * H + 9 * j + L;           // addr1(64H+8j+L)
            xr[j] = Sr[a];
            xi[j] = Si[a];
        }
        { float2 w = d_tw[L << 5];
          BFLY(0,1,w); BFLY(2,3,w); BFLY(4,5,w); BFLY(6,7,w); }
        { float2 w0 = d_tw[L << 4], w1 = d_tw[(8 + L) << 4];
          BFLY(0,2,w0); BFLY(1,3,w1); BFLY(4,6,w0); BFLY(5,7,w1); }
        { float2 w0 = d_tw[L << 3],        w1 = d_tw[(8 + L) << 3];
          float2 w2 = d_tw[(16 + L) << 3], w3 = d_tw[(24 + L) << 3];
          BFLY(0,4,w0); BFLY(1,5,w1); BFLY(2,6,w2); BFLY(3,7,w3); }
        GBAR();
        #pragma unroll
        for (int j = 0; j < 8; j++) {             // addr2(64H+8j+L)
            Sr[72 * j + 9 * L + H] = xr[j];
            Si[72 * j + 9 * L + H] = xi[j];
        }
        GBAR();

        // ---- phase C: i = 64j + gt, stages 7-9, natural order out ----
        #pragma unroll
        for (int j = 0; j < 8; j++) {
            int a = 9 * gt + j;                   // addr2(64j+gt)
            xr[j] = Sr[a];
            xi[j] = Si[a];
        }
        { float2 w = d_tw[gt << 2];
          BFLY(0,1,w); BFLY(2,3,w); BFLY(4,5,w); BFLY(6,7,w); }
        { float2 w0 = d_tw[gt << 1], w1 = d_tw[(64 + gt) << 1];
          BFLY(0,2,w0); BFLY(1,3,w1); BFLY(4,6,w0); BFLY(5,7,w1); }
        { float2 w0 = d_tw[gt],       w1 = d_tw[64 + gt];
          float2 w2 = d_tw[128 + gt], w3 = d_tw[192 + gt];
          BFLY(0,4,w0); BFLY(1,5,w1); BFLY(2,6,w2); BFLY(3,7,w3); }
        GBAR();
        #pragma unroll
        for (int j = 0; j < 8; j++) {             // plain Z[64j+gt]
            Sr[64 * j + gt] = xr[j];
            Si[64 * j + gt] = xi[j];
        }
        GBAR();

        // ---- untangle: bin k = 64rr+gt (own Zk in regs); (0,0) -> 512 ----
        #pragma unroll
        for (int rr = 0; rr < 8; rr++) {
            int k = 64 * rr + gt;
            float zkr = xr[rr], zki = xi[rr];     // Z[k&511], own register
            float zmr, zmi;
            if (k == 0) {                          // bin 512: Zm = Z[0] = Zk
                k = 512;
                zmr = zkr; zmi = zki;
            } else {                               // Zm = Z[512-k] from smem
                int km = 512 - k;                  // 1..511
                zmr = Sr[km]; zmi = Si[km];
            }
            float ar = 0.5f * (zkr + zmr);
            float ai = 0.5f * (zki - zmi);
            float br = 0.5f * (zkr - zmr);
            float bi = 0.5f * (zki + zmi);
            float2 C = d_unt[k];
            float vr = ar + C.x * br - C.y * bi;
            float vi = ai + C.x * bi + C.y * br;
            if (k == 512) vi = 0.0f;              // Nyquist analytically real
            ph[f * 513 + (k - 1)] = atan2f(vi, vr);
            if (f >= 1) {
                float m2 = vr * vr + vi * vi;
                mg[(f - 1) * 513 + (k - 1)] = __float2half_rn(
                    (0.5f * __logf(fmaxf(m2, 1e-14f)) + 17.0f) * (1.0f / 23.0f));
            }
        }
        GBAR();    // S reused by next round's load
    }

    __syncthreads();   // staging (ph/mg) is read across groups below

    // ---- writeback: per-thread 8 consecutive t's, float4 stores ----
    const float PI_F   = 3.14159274101257324f;
    const float TWO_PI = 6.28318548202514648f;

    for (int fo = tid; fo < FOUT; fo += 192) {
        size_t omag = (((size_t)b * 2 + 0) * FOUT + fo) * TOUT + FPB * g;
        size_t opha = (((size_t)b * 2 + 1) * FOUT + fo) * TOUT + FPB * g;

        float m[FPB], p[FPB];
        #pragma unroll
        for (int j = 0; j < FPB; j++) {
            m[j] = __half2float(mg[j * 513 + fo]);
            float p0 = ph[j * 513 + fo];
            float p1 = ph[(j + 1) * 513 + fo];
            float dd = p1 - p0;
            float res;
            if (fabsf(dd) < PI_F) {
                res = dd;
            } else {
                float rr = fmodf(dd + PI_F, TWO_PI);
                if (rr < 0.0f) rr += TWO_PI;
                float ddmod = rr - PI_F;
                if (ddmod == -PI_F && dd > 0.0f) ddmod = PI_F;
                res = ddmod;
            }
            p[j] = res;
        }
        *reinterpret_cast<float4*>(out + omag) =
            make_float4(m[0], m[1], m[2], m[3]);
        *reinterpret_cast<float4*>(out + omag + 4) =
            make_float4(m[4], m[5], m[6], m[7]);
        *reinterpret_cast<float4*>(out + opha) =
            make_float4(p[0], p[1], p[2], p[3]);
        *reinterpret_cast<float4*>(out + opha + 4) =
            make_float4(p[4], p[5], p[6], p[7]);
    }
}

extern "C" void kernel_launch(void* const* d_in, const int* in_sizes, int n_in,
                              void* d_out, int out_size)
{
    const float* x = (const float*)d_in[0];
    float* out = (float*)d_out;

    // exchange 3*2*576*4 + ph 9*513*4 + mg 8*513*2 = 40500 B
    const int smem_bytes = (3 * 2 * SBUF + 9 * 513) * 4 + 8 * 513 * 2;
    cudaFuncSetAttribute(stft_fused_kernel,
                         cudaFuncAttributeMaxDynamicSharedMemorySize,
                         smem_bytes);

    init_tables_kernel<<<8, 128>>>();

    dim3 grid(TOUT / FPB, NB);     // (256, 32)
    stft_fused_kernel<<<grid, 192, smem_bytes>>>(x, out);
}